// round 5
// baseline (speedup 1.0000x reference)
#include <cuda_runtime.h>

#define B 16
#define CIN 32
#define COUT 32
#define H 256
#define W 256
#define KM 16

// Persistent scratch (no cudaMalloc allowed)
__device__ float2 g_tab[256];              // (cos(2*pi*k/256), sin(2*pi*k/256))
__device__ float2 g_D[256];                // D(h) = sum_{m<16} e^{-2*pi*i*m*h/256}
__device__ float2 g_S[B][CIN][KM];         // column-frequency sums
__device__ float2 g_U[B][COUT][KM][W];     // per-(b,o) row spectra u[m][w]  (~16.8 MB)

__global__ void k_init() {
    int k = threadIdx.x;
    double ang = 2.0 * 3.141592653589793238462643 * (double)k / 256.0;
    g_tab[k] = make_float2((float)cos(ang), (float)sin(ang));
    double dr = 0.0, di = 0.0;
    for (int m = 0; m < 16; m++) {
        double a = ang * (double)m;
        dr += cos(a);
        di -= sin(a);
    }
    g_D[k] = make_float2((float)dr, (float)di);
}

// Phase A: z[b,i,w] = sum_h D(h) x[b,i,h,w]; S[b,i,n] = (1/256) sum_w z e^{-2pi i n w/256}
__global__ void k_analysis(const float* __restrict__ x) {
    __shared__ float2 sD[256];
    __shared__ float2 sT[256];
    __shared__ float2 sz[256];
    int t = threadIdx.x;
    int i = blockIdx.x, b = blockIdx.y;
    sD[t] = g_D[t];
    sT[t] = g_tab[t];
    __syncthreads();

    const float* xp = x + (size_t)(b * CIN + i) * (H * W) + t;
    float zr = 0.f, zi = 0.f;
#pragma unroll 8
    for (int h = 0; h < H; h++) {
        float v = xp[h << 8];
        float2 d = sD[h];
        zr = fmaf(d.x, v, zr);
        zi = fmaf(d.y, v, zi);
    }
    sz[t] = make_float2(zr, zi);
    __syncthreads();

    int n = t >> 4, j = t & 15;
    float pr = 0.f, pi = 0.f;
#pragma unroll
    for (int q = 0; q < 16; q++) {
        int w = q * 16 + j;
        float2 z = sz[w];
        float2 cs = sT[(n * w) & 255];
        // z * e^{-i theta} = (zr*c + zi*s) + i(zi*c - zr*s)
        pr += z.x * cs.x + z.y * cs.y;
        pi += z.y * cs.x - z.x * cs.y;
    }
#pragma unroll
    for (int d = 8; d > 0; d >>= 1) {
        pr += __shfl_down_sync(0xffffffffu, pr, d, 16);
        pi += __shfl_down_sync(0xffffffffu, pi, d, 16);
    }
    if (j == 0)
        g_S[b][i][n] = make_float2(pr * (1.f / 256.f), pi * (1.f / 256.f));
}

// Phase B: g[m,n] = sum_i S[b,i,m]*(wr + i wi)[i,o,m,n];
// then u[m,w] = g[m,0] + 2*sum_{n=1..15} g[m,n] e^{+2pi i n w/256}
__global__ void k_mix(const float* __restrict__ Wr, const float* __restrict__ Wi) {
    __shared__ float2 sS[CIN * KM];  // [i][m]
    __shared__ float2 sG[KM * KM];   // [m][n]
    __shared__ float2 sT[256];
    int t = threadIdx.x;
    int o = blockIdx.x, b = blockIdx.y;
    sT[t] = g_tab[t];
    const float2* Sp = &g_S[b][0][0];
    sS[t] = Sp[t];
    sS[t + 256] = Sp[t + 256];
    __syncthreads();

    int m = t >> 4, n = t & 15;
    float gr = 0.f, gi = 0.f;
    int off = (o * KM + m) * KM + n;   // [i=0][o][m][n]
#pragma unroll 4
    for (int i = 0; i < CIN; i++) {
        float2 s = sS[i * KM + m];     // S indexed by ROW freq m
        float wr = Wr[off], wi = Wi[off];
        gr += s.x * wr - s.y * wi;
        gi += s.x * wi + s.y * wr;
        off += COUT * KM * KM;         // +8192
    }
    sG[t] = make_float2(gr, gi);
    __syncthreads();

    int w = t;
#pragma unroll
    for (int mm = 0; mm < KM; mm++) {
        float2 g0 = sG[mm * 16];
        float ur = g0.x, ui = g0.y;
#pragma unroll
        for (int nn = 1; nn < 16; nn++) {
            float2 cs = sT[(nn * w) & 255];
            float2 g = sG[mm * 16 + nn];
            // g * e^{+i theta}: (gr*c - gi*s) + i(gr*s + gi*c), doubled (hermitian fold)
            ur += 2.f * (g.x * cs.x - g.y * cs.y);
            ui += 2.f * (g.x * cs.y + g.y * cs.x);
        }
        g_U[b][o][mm][w] = make_float2(ur, ui);
    }
}

// Phase C: y[h,w] = (1/256) sum_m ( ur[m,w] cos(2pi m h/256) - ui[m,w] sin(2pi m h/256) )
// 4-fold row symmetry: one 32-FMA pass over m yields rows {h, 256-h, 128+h, 128-h}.
__global__ void k_synth(float* __restrict__ y) {
    __shared__ float2 sT[256];
    int t = threadIdx.x;
    int o = blockIdx.x, b = blockIdx.y, hc = blockIdx.z;
    sT[t] = g_tab[t];
    float ur[16], ui[16];
#pragma unroll
    for (int m = 0; m < 16; m++) {
        float2 v = g_U[b][o][m][t];
        ur[m] = v.x;
        ui[m] = v.y;
    }
    __syncthreads();

    float* yp = y + (size_t)(b * COUT + o) * (H * W) + t;
    const float inv = 1.f / 256.f;
    int h0 = hc * 13;
    int h1 = h0 + 13;
    if (h1 > 65) h1 = 65;
    for (int h = h0; h < h1; h++) {
        float ae = 0.f, ao = 0.f, be = 0.f, bo = 0.f;
#pragma unroll
        for (int m = 0; m < 16; m += 2) {
            float2 cs0 = sT[(m * h) & 255];
            float2 cs1 = sT[((m + 1) * h) & 255];
            ae = fmaf(ur[m], cs0.x, ae);
            be = fmaf(ui[m], cs0.y, be);
            ao = fmaf(ur[m + 1], cs1.x, ao);
            bo = fmaf(ui[m + 1], cs1.y, bo);
        }
        float s  = ae + ao;   // cos part, all m
        float d2 = ae - ao;   // cos part with (-1)^m
        float sb = be + bo;   // sin part, all m
        float db = be - bo;   // sin part with (-1)^m
        yp[(size_t)h * W]         = (s - sb) * inv;   // row h
        yp[(size_t)(128 + h) * W] = (d2 - db) * inv;  // row 128+h
        if (h > 0 && h < 64) {
            yp[(size_t)(256 - h) * W] = (s + sb) * inv;   // row 256-h
            yp[(size_t)(128 - h) * W] = (d2 + db) * inv;  // row 128-h
        }
    }
}

extern "C" void kernel_launch(void* const* d_in, const int* in_sizes, int n_in,
                              void* d_out, int out_size) {
    (void)in_sizes; (void)n_in; (void)out_size;
    const float* x  = (const float*)d_in[0];
    const float* wr = (const float*)d_in[1];
    const float* wi = (const float*)d_in[2];
    float* y = (float*)d_out;

    k_init<<<1, 256>>>();
    k_analysis<<<dim3(CIN, B), 256>>>(x);
    k_mix<<<dim3(COUT, B), 256>>>(wr, wi);
    k_synth<<<dim3(COUT, B, 5), 256>>>(y);
}

// round 9
// speedup vs baseline: 1.0424x; 1.0424x over previous
#include <cuda_runtime.h>

#define B 16
#define CIN 32
#define COUT 32
#define H 256
#define W 256
#define KM 16

typedef unsigned long long ull;

// Persistent scratch (no cudaMalloc allowed)
__device__ float2 g_tab[256];               // (cos(2*pi*k/256), sin(2*pi*k/256))
__device__ float2 g_D[256];                 // D(h) = sum_{m<16} e^{-2*pi*i*m*h/256}
__device__ float2 g_Sp[4][B][CIN][KM];      // per-h-chunk partial column-frequency sums
__device__ float2 g_U[B][COUT][KM][W];      // per-(b,o) row spectra u[m][w], pre-scaled by 1/256

#define FMA_F32X2(d, a, b, c) \
    asm("fma.rn.f32x2 %0, %1, %2, %3;" : "=l"(d) : "l"(a), "l"(b), "l"(c))

__global__ void k_init() {
    int k = threadIdx.x;
    double ang = 2.0 * 3.141592653589793238462643 * (double)k / 256.0;
    g_tab[k] = make_float2((float)cos(ang), (float)sin(ang));
    double dr = 0.0, di = 0.0;
    for (int m = 0; m < 16; m++) {
        double a = ang * (double)m;
        dr += cos(a);
        di -= sin(a);
    }
    g_D[k] = make_float2((float)dr, (float)di);
}

// Phase A: partial z over a 64-row chunk, then 16-point w-DFT of the partial.
// z[b,i,w] = sum_h D(h) x[b,i,h,w];  S_partial[n] = (1/256) sum_w z_part e^{-2pi i n w/256}
__global__ void k_analysis(const float* __restrict__ x) {
    __shared__ float2 sD[64];
    __shared__ float2 sT[256];
    __shared__ float2 spart[4][256];
    __shared__ float2 sz[256];
    int t = threadIdx.x;
    int i = blockIdx.x, b = blockIdx.y, ch = blockIdx.z;

    sT[t] = g_tab[t];
    if (t < 64) sD[t] = g_D[ch * 64 + t];
    __syncthreads();

    int wq = t & 63;        // float4 column index (w = wq*4 .. wq*4+3)
    int sub = t >> 6;       // 16-row subgroup within the 64-row chunk
    const float4* xp = (const float4*)(x + ((size_t)(b * CIN + i) << 16))
                       + (size_t)(ch * 64 + sub * 16) * 64 + wq;

    float zr0 = 0.f, zr1 = 0.f, zr2 = 0.f, zr3 = 0.f;
    float zi0 = 0.f, zi1 = 0.f, zi2 = 0.f, zi3 = 0.f;
#pragma unroll
    for (int r = 0; r < 16; r++) {
        float4 v = xp[r * 64];
        float2 d = sD[sub * 16 + r];
        zr0 = fmaf(d.x, v.x, zr0); zi0 = fmaf(d.y, v.x, zi0);
        zr1 = fmaf(d.x, v.y, zr1); zi1 = fmaf(d.y, v.y, zi1);
        zr2 = fmaf(d.x, v.z, zr2); zi2 = fmaf(d.y, v.z, zi2);
        zr3 = fmaf(d.x, v.w, zr3); zi3 = fmaf(d.y, v.w, zi3);
    }
    spart[sub][wq * 4 + 0] = make_float2(zr0, zi0);
    spart[sub][wq * 4 + 1] = make_float2(zr1, zi1);
    spart[sub][wq * 4 + 2] = make_float2(zr2, zi2);
    spart[sub][wq * 4 + 3] = make_float2(zr3, zi3);
    __syncthreads();

    float2 a0 = spart[0][t], a1 = spart[1][t], a2 = spart[2][t], a3 = spart[3][t];
    sz[t] = make_float2((a0.x + a1.x) + (a2.x + a3.x), (a0.y + a1.y) + (a2.y + a3.y));
    __syncthreads();

    int n = t >> 4, j = t & 15;
    float pr = 0.f, pi = 0.f;
#pragma unroll
    for (int q = 0; q < 16; q++) {
        int w = q * 16 + j;
        float2 z = sz[w];
        float2 cs = sT[(n * w) & 255];
        // z * e^{-i theta} = (zr*c + zi*s) + i(zi*c - zr*s)
        pr += z.x * cs.x + z.y * cs.y;
        pi += z.y * cs.x - z.x * cs.y;
    }
#pragma unroll
    for (int d = 8; d > 0; d >>= 1) {
        pr += __shfl_down_sync(0xffffffffu, pr, d, 16);
        pi += __shfl_down_sync(0xffffffffu, pi, d, 16);
    }
    if (j == 0)
        g_Sp[ch][b][i][n] = make_float2(pr * (1.f / 256.f), pi * (1.f / 256.f));
}

// Phase B: sum S partials; g[m,n] = sum_i S[b,i,m]*(wr + i wi)[i,o,m,n];
// u[m,w] = (1/256)*(g[m,0] + 2*sum_{n=1..15} g[m,n] e^{+2pi i n w/256})
// Each block handles 4 of the 16 m values (blockIdx.z chunk).
__global__ void k_mix(const float* __restrict__ Wr, const float* __restrict__ Wi) {
    __shared__ float2 sS[CIN * KM];  // [i][m]
    __shared__ float2 sG[4 * KM];    // [ml][n]
    __shared__ float2 sT[256];
    int t = threadIdx.x;
    int o = blockIdx.x, b = blockIdx.y, mc = blockIdx.z;
    sT[t] = g_tab[t];

    const float2* sp = &g_Sp[0][b][0][0];
    const int CHS = B * CIN * KM;  // chunk stride in float2
#pragma unroll
    for (int e = t; e < CIN * KM; e += 256) {
        float2 p0 = sp[e], p1 = sp[CHS + e], p2 = sp[2 * CHS + e], p3 = sp[3 * CHS + e];
        sS[e] = make_float2((p0.x + p1.x) + (p2.x + p3.x), (p0.y + p1.y) + (p2.y + p3.y));
    }
    __syncthreads();

    if (t < 64) {
        int ml = t >> 4, n = t & 15;
        int m = mc * 4 + ml;
        float gr = 0.f, gi = 0.f;
        int off = (o * KM + m) * KM + n;   // [i=0][o][m][n]
#pragma unroll 4
        for (int i = 0; i < CIN; i++) {
            float2 s = sS[i * KM + m];
            float wr = Wr[off], wi = Wi[off];
            gr += s.x * wr - s.y * wi;
            gi += s.x * wi + s.y * wr;
            off += COUT * KM * KM;         // +8192
        }
        sG[ml * 16 + n] = make_float2(gr, gi);
    }
    __syncthreads();

    int w = t;
    const float inv = 1.f / 256.f;
#pragma unroll
    for (int ml = 0; ml < 4; ml++) {
        float2 g0 = sG[ml * 16];
        float ur = g0.x, ui = g0.y;
#pragma unroll
        for (int nn = 1; nn < 16; nn++) {
            float2 cs = sT[(nn * w) & 255];
            float2 g = sG[ml * 16 + nn];
            ur += 2.f * (g.x * cs.x - g.y * cs.y);
            ui += 2.f * (g.x * cs.y + g.y * cs.x);
        }
        g_U[b][o][mc * 4 + ml][w] = make_float2(ur * inv, ui * inv);
    }
}

// Phase C: y[h,w] = sum_m ( ur'[m,w] cos(2pi m h/256) - ui'[m,w] sin(2pi m h/256) )
// (u' pre-scaled by 1/256). 4-fold row symmetry; packed f32x2 FMA:
// accE/accO accumulate (sum ur'*c, sum ui'*s) over even/odd m.
__global__ void k_synth(float* __restrict__ y) {
    __shared__ float2 sHT[13 * 16];   // per-block twiddles: [lh][m] = g_tab[(m*h)&255]
    int t = threadIdx.x;
    int o = blockIdx.x, b = blockIdx.y, hc = blockIdx.z;
    int h0 = hc * 13;

    if (t < 208) {
        int lh = t >> 4, m = t & 15;
        sHT[t] = g_tab[(m * (h0 + lh)) & 255];
    }

    ull u2[16];
    const ull* up = (const ull*)&g_U[b][o][0][t];
#pragma unroll
    for (int m = 0; m < 16; m++) u2[m] = up[m * W];
    __syncthreads();

    float* yp = y + ((size_t)(b * COUT + o) << 16) + t;
#pragma unroll 2
    for (int lh = 0; lh < 13; lh++) {
        int h = h0 + lh;
        const ull* tp = (const ull*)&sHT[lh * 16];
        ull aE = 0ull, aO = 0ull;
#pragma unroll
        for (int m = 0; m < 16; m += 2) {
            FMA_F32X2(aE, u2[m], tp[m], aE);
            FMA_F32X2(aO, u2[m + 1], tp[m + 1], aO);
        }
        float Ae, Be, Ao, Bo;
        asm("mov.b64 {%0, %1}, %2;" : "=f"(Ae), "=f"(Be) : "l"(aE));
        asm("mov.b64 {%0, %1}, %2;" : "=f"(Ao), "=f"(Bo) : "l"(aO));
        float u1 = Ae - Be, v1 = Ao - Bo;   // cos-part minus sin-part, even/odd m
        float p1 = Ae + Be, q1 = Ao + Bo;
        yp[h << 8] = u1 + v1;               // row h
        yp[(128 + h) << 8] = u1 - v1;       // row 128+h
        if (h > 0 && h < 64) {
            yp[(256 - h) << 8] = p1 + q1;   // row 256-h
            yp[(128 - h) << 8] = p1 - q1;   // row 128-h
        }
    }
}

extern "C" void kernel_launch(void* const* d_in, const int* in_sizes, int n_in,
                              void* d_out, int out_size) {
    (void)in_sizes; (void)n_in; (void)out_size;
    const float* x  = (const float*)d_in[0];
    const float* wr = (const float*)d_in[1];
    const float* wi = (const float*)d_in[2];
    float* y = (float*)d_out;

    k_init<<<1, 256>>>();
    k_analysis<<<dim3(CIN, B, 4), 256>>>(x);
    k_mix<<<dim3(COUT, B, 4), 256>>>(wr, wi);
    k_synth<<<dim3(COUT, B, 5), 256>>>(y);
}

// round 10
// speedup vs baseline: 1.7396x; 1.6687x over previous
#include <cuda_runtime.h>

#define B 16
#define CIN 32
#define COUT 32
#define H 256
#define W 256
#define KM 16

typedef unsigned long long ull;

// Persistent scratch (no cudaMalloc allowed)
__device__ float2 g_Sp[4][B][CIN][KM];      // per-h-chunk partial column-frequency sums
__device__ float2 g_U[B][COUT][KM][W];      // per-(b,o) row spectra u[m][w], pre-scaled by 1/256

#define FMA_F32X2(d, a, b, c) \
    asm("fma.rn.f32x2 %0, %1, %2, %3;" : "=l"(d) : "l"(a), "l"(b), "l"(c))

// twiddle (cos, sin) of 2*pi*k/256 = pi*k/128, k need not be pre-masked
__device__ __forceinline__ float2 twiddle(int k) {
    float s, c;
    sincospif((float)(k & 255) * (1.0f / 128.0f), &s, &c);
    return make_float2(c, s);
}

// Phase A: partial z over a 64-row chunk, then 16-point w-DFT of the partial.
// z[b,i,w] = sum_h D(h) x[b,i,h,w];  S_partial[n] = (1/256) sum_w z_part e^{-2pi i n w/256}
// D(h) = sum_{m<16} e^{-i m theta} = e^{-i 7.5 theta} * sin(8 theta)/sin(theta/2), theta = pi h/128
__global__ void k_analysis(const float* __restrict__ x) {
    __shared__ float2 sD[64];
    __shared__ float2 sT[256];
    __shared__ float2 spart[4][256];
    __shared__ float2 sz[256];
    int t = threadIdx.x;
    int i = blockIdx.x, b = blockIdx.y, ch = blockIdx.z;

    sT[t] = twiddle(t);
    if (t < 64) {
        int h = ch * 64 + t;
        if (h == 0) {
            sD[t] = make_float2(16.f, 0.f);
        } else {
            float num = sinpif((float)h * (1.0f / 16.0f));    // sin(8 theta)
            float den = sinpif((float)h * (1.0f / 256.0f));   // sin(theta/2)
            float R = num / den;
            float s, c;
            sincospif((float)h * (15.0f / 256.0f), &s, &c);   // 7.5 theta = pi*15h/256
            sD[t] = make_float2(c * R, -s * R);
        }
    }
    __syncthreads();

    int wq = t & 63;        // float4 column index (w = wq*4 .. wq*4+3)
    int sub = t >> 6;       // 16-row subgroup within the 64-row chunk
    const float4* xp = (const float4*)(x + ((size_t)(b * CIN + i) << 16))
                       + (size_t)(ch * 64 + sub * 16) * 64 + wq;

    float zr0 = 0.f, zr1 = 0.f, zr2 = 0.f, zr3 = 0.f;
    float zi0 = 0.f, zi1 = 0.f, zi2 = 0.f, zi3 = 0.f;
#pragma unroll
    for (int r = 0; r < 16; r++) {
        float4 v = __ldcs(&xp[r * 64]);
        float2 d = sD[sub * 16 + r];
        zr0 = fmaf(d.x, v.x, zr0); zi0 = fmaf(d.y, v.x, zi0);
        zr1 = fmaf(d.x, v.y, zr1); zi1 = fmaf(d.y, v.y, zi1);
        zr2 = fmaf(d.x, v.z, zr2); zi2 = fmaf(d.y, v.z, zi2);
        zr3 = fmaf(d.x, v.w, zr3); zi3 = fmaf(d.y, v.w, zi3);
    }
    spart[sub][wq * 4 + 0] = make_float2(zr0, zi0);
    spart[sub][wq * 4 + 1] = make_float2(zr1, zi1);
    spart[sub][wq * 4 + 2] = make_float2(zr2, zi2);
    spart[sub][wq * 4 + 3] = make_float2(zr3, zi3);
    __syncthreads();

    float2 a0 = spart[0][t], a1 = spart[1][t], a2 = spart[2][t], a3 = spart[3][t];
    sz[t] = make_float2((a0.x + a1.x) + (a2.x + a3.x), (a0.y + a1.y) + (a2.y + a3.y));
    __syncthreads();

    int n = t >> 4, j = t & 15;
    float pr = 0.f, pi = 0.f;
#pragma unroll
    for (int q = 0; q < 16; q++) {
        int w = q * 16 + j;
        float2 z = sz[w];
        float2 cs = sT[(n * w) & 255];
        // z * e^{-i theta} = (zr*c + zi*s) + i(zi*c - zr*s)
        pr += z.x * cs.x + z.y * cs.y;
        pi += z.y * cs.x - z.x * cs.y;
    }
#pragma unroll
    for (int d = 8; d > 0; d >>= 1) {
        pr += __shfl_down_sync(0xffffffffu, pr, d, 16);
        pi += __shfl_down_sync(0xffffffffu, pi, d, 16);
    }
    if (j == 0)
        g_Sp[ch][b][i][n] = make_float2(pr * (1.f / 256.f), pi * (1.f / 256.f));
}

// Phase B: sum S partials; g[m,n] = sum_i S[b,i,m]*(wr + i wi)[i,o,m,n];
// u[m,w] = (1/256)*(g[m,0] + 2*sum_{n=1..15} g[m,n] e^{+2pi i n w/256})
// Each block handles 4 of the 16 m values (blockIdx.z chunk).
__global__ void k_mix(const float* __restrict__ Wr, const float* __restrict__ Wi) {
    __shared__ float2 sS[CIN * KM];  // [i][m]
    __shared__ float2 sG[4 * KM];    // [ml][n]
    __shared__ float2 sT[256];
    int t = threadIdx.x;
    int o = blockIdx.x, b = blockIdx.y, mc = blockIdx.z;
    sT[t] = twiddle(t);

    const float2* sp = &g_Sp[0][b][0][0];
    const int CHS = B * CIN * KM;  // chunk stride in float2
#pragma unroll
    for (int e = t; e < CIN * KM; e += 256) {
        float2 p0 = sp[e], p1 = sp[CHS + e], p2 = sp[2 * CHS + e], p3 = sp[3 * CHS + e];
        sS[e] = make_float2((p0.x + p1.x) + (p2.x + p3.x), (p0.y + p1.y) + (p2.y + p3.y));
    }
    __syncthreads();

    if (t < 64) {
        int ml = t >> 4, n = t & 15;
        int m = mc * 4 + ml;
        float gr = 0.f, gi = 0.f;
        int off = (o * KM + m) * KM + n;   // [i=0][o][m][n]
#pragma unroll 4
        for (int i = 0; i < CIN; i++) {
            float2 s = sS[i * KM + m];
            float wr = Wr[off], wi = Wi[off];
            gr += s.x * wr - s.y * wi;
            gi += s.x * wi + s.y * wr;
            off += COUT * KM * KM;         // +8192
        }
        sG[ml * 16 + n] = make_float2(gr, gi);
    }
    __syncthreads();

    int w = t;
    const float inv = 1.f / 256.f;
#pragma unroll
    for (int ml = 0; ml < 4; ml++) {
        float2 g0 = sG[ml * 16];
        float ur = g0.x, ui = g0.y;
#pragma unroll
        for (int nn = 1; nn < 16; nn++) {
            float2 cs = sT[(nn * w) & 255];
            float2 g = sG[ml * 16 + nn];
            ur += 2.f * (g.x * cs.x - g.y * cs.y);
            ui += 2.f * (g.x * cs.y + g.y * cs.x);
        }
        g_U[b][o][mc * 4 + ml][w] = make_float2(ur * inv, ui * inv);
    }
}

// Phase C: y[h,w] = sum_m ( ur'[m,w] cos(2pi m h/256) - ui'[m,w] sin(2pi m h/256) )
// (u' pre-scaled by 1/256). 4-fold row symmetry; packed f32x2 FMA:
// accE/accO accumulate (sum ur'*c, sum ui'*s) over even/odd m.
__global__ void k_synth(float* __restrict__ y) {
    __shared__ float2 sHT[13 * 16];   // per-block twiddles: [lh][m] = twiddle(m*h)
    int t = threadIdx.x;
    int o = blockIdx.x, b = blockIdx.y, hc = blockIdx.z;
    int h0 = hc * 13;

    if (t < 208) {
        int lh = t >> 4, m = t & 15;
        sHT[t] = twiddle(m * (h0 + lh));
    }

    ull u2[16];
    const ull* up = (const ull*)&g_U[b][o][0][t];
#pragma unroll
    for (int m = 0; m < 16; m++) u2[m] = up[m * W];
    __syncthreads();

    float* yp = y + ((size_t)(b * COUT + o) << 16) + t;
#pragma unroll 2
    for (int lh = 0; lh < 13; lh++) {
        int h = h0 + lh;
        const ull* tp = (const ull*)&sHT[lh * 16];
        ull aE = 0ull, aO = 0ull;
#pragma unroll
        for (int m = 0; m < 16; m += 2) {
            FMA_F32X2(aE, u2[m], tp[m], aE);
            FMA_F32X2(aO, u2[m + 1], tp[m + 1], aO);
        }
        float Ae, Be, Ao, Bo;
        asm("mov.b64 {%0, %1}, %2;" : "=f"(Ae), "=f"(Be) : "l"(aE));
        asm("mov.b64 {%0, %1}, %2;" : "=f"(Ao), "=f"(Bo) : "l"(aO));
        float u1 = Ae - Be, v1 = Ao - Bo;   // cos-part minus sin-part, even/odd m
        float p1 = Ae + Be, q1 = Ao + Bo;
        yp[h << 8] = u1 + v1;               // row h
        yp[(128 + h) << 8] = u1 - v1;       // row 128+h
        if (h > 0 && h < 64) {
            yp[(256 - h) << 8] = p1 + q1;   // row 256-h
            yp[(128 - h) << 8] = p1 - q1;   // row 128-h
        }
    }
}

extern "C" void kernel_launch(void* const* d_in, const int* in_sizes, int n_in,
                              void* d_out, int out_size) {
    (void)in_sizes; (void)n_in; (void)out_size;
    const float* x  = (const float*)d_in[0];
    const float* wr = (const float*)d_in[1];
    const float* wi = (const float*)d_in[2];
    float* y = (float*)d_out;

    k_analysis<<<dim3(CIN, B, 4), 256>>>(x);
    k_mix<<<dim3(COUT, B, 4), 256>>>(wr, wi);
    k_synth<<<dim3(COUT, B, 5), 256>>>(y);
}

// round 15
// speedup vs baseline: 2.0888x; 1.2007x over previous
#include <cuda_runtime.h>

#define B 16
#define CIN 32
#define COUT 32
#define H 256
#define W 256
#define KM 16

typedef unsigned long long ull;

// Persistent scratch (no cudaMalloc allowed)
__device__ float2 g_Sp[4][B][CIN][KM];      // per-h-chunk partial column-frequency sums
__device__ float2 g_U[B][COUT][KM][W];      // per-(b,o) row spectra u[m][w], pre-scaled by 1/256

#define FMA_F32X2(d, a, b, c) \
    asm("fma.rn.f32x2 %0, %1, %2, %3;" : "=l"(d) : "l"(a), "l"(b), "l"(c))

// twiddle (cos, sin) of 2*pi*k/256 = pi*k/128, k need not be pre-masked
__device__ __forceinline__ float2 twiddle(int k) {
    float s, c;
    sincospif((float)(k & 255) * (1.0f / 128.0f), &s, &c);
    return make_float2(c, s);
}

// Phase A: partial z over a 64-row chunk, then 16-point w-DFT of the partial.
// z[b,i,w] = sum_h D(h) x[b,i,h,w];  S_partial[n] = (1/256) sum_w z_part e^{-2pi i n w/256}
// D(h) = sum_{m<16} e^{-i m theta} = e^{-i 7.5 theta} * sin(8 theta)/sin(theta/2), theta = pi h/128
__global__ void k_analysis(const float* __restrict__ x) {
    __shared__ float2 sD[64];
    __shared__ float2 sT[256];
    __shared__ float2 spart[4][256];
    __shared__ float2 sz[256];
    int t = threadIdx.x;
    int i = blockIdx.x, b = blockIdx.y, ch = blockIdx.z;

    if (t < 64) {
        int h = ch * 64 + t;
        if (h == 0) {
            sD[t] = make_float2(16.f, 0.f);
        } else {
            float num = sinpif((float)h * (1.0f / 16.0f));    // sin(8 theta)
            float den = sinpif((float)h * (1.0f / 256.0f));   // sin(theta/2)
            float R = num / den;
            float s, c;
            sincospif((float)h * (15.0f / 256.0f), &s, &c);   // 7.5 theta = pi*15h/256
            sD[t] = make_float2(c * R, -s * R);
        }
    }
    __syncthreads();

    int wq = t & 63;        // float4 column index (w = wq*4 .. wq*4+3)
    int sub = t >> 6;       // 16-row subgroup within the 64-row chunk
    const float4* xp = (const float4*)(x + ((size_t)(b * CIN + i) << 16))
                       + (size_t)(ch * 64 + sub * 16) * 64 + wq;

    float zr0 = 0.f, zr1 = 0.f, zr2 = 0.f, zr3 = 0.f;
    float zi0 = 0.f, zi1 = 0.f, zi2 = 0.f, zi3 = 0.f;
#pragma unroll
    for (int r = 0; r < 16; r += 4) {
        // 4 loads issued back-to-back (MLP batch) before the consuming FMAs
        float4 v[4];
        float2 d[4];
#pragma unroll
        for (int u = 0; u < 4; u++) v[u] = __ldcs(&xp[(r + u) * 64]);
#pragma unroll
        for (int u = 0; u < 4; u++) d[u] = sD[sub * 16 + r + u];
#pragma unroll
        for (int u = 0; u < 4; u++) {
            zr0 = fmaf(d[u].x, v[u].x, zr0); zi0 = fmaf(d[u].y, v[u].x, zi0);
            zr1 = fmaf(d[u].x, v[u].y, zr1); zi1 = fmaf(d[u].y, v[u].y, zi1);
            zr2 = fmaf(d[u].x, v[u].z, zr2); zi2 = fmaf(d[u].y, v[u].z, zi2);
            zr3 = fmaf(d[u].x, v[u].w, zr3); zi3 = fmaf(d[u].y, v[u].w, zi3);
        }
    }
    sT[t] = twiddle(t);   // off the pre-load critical path; ready before next sync
    spart[sub][wq * 4 + 0] = make_float2(zr0, zi0);
    spart[sub][wq * 4 + 1] = make_float2(zr1, zi1);
    spart[sub][wq * 4 + 2] = make_float2(zr2, zi2);
    spart[sub][wq * 4 + 3] = make_float2(zr3, zi3);
    __syncthreads();

    float2 a0 = spart[0][t], a1 = spart[1][t], a2 = spart[2][t], a3 = spart[3][t];
    sz[t] = make_float2((a0.x + a1.x) + (a2.x + a3.x), (a0.y + a1.y) + (a2.y + a3.y));
    __syncthreads();

    int n = t >> 4, j = t & 15;
    float pr = 0.f, pi = 0.f;
#pragma unroll
    for (int q = 0; q < 16; q++) {
        int w = q * 16 + j;
        float2 z = sz[w];
        float2 cs = sT[(n * w) & 255];
        // z * e^{-i theta} = (zr*c + zi*s) + i(zi*c - zr*s)
        pr += z.x * cs.x + z.y * cs.y;
        pi += z.y * cs.x - z.x * cs.y;
    }
#pragma unroll
    for (int d = 8; d > 0; d >>= 1) {
        pr += __shfl_down_sync(0xffffffffu, pr, d, 16);
        pi += __shfl_down_sync(0xffffffffu, pi, d, 16);
    }
    if (j == 0)
        g_Sp[ch][b][i][n] = make_float2(pr * (1.f / 256.f), pi * (1.f / 256.f));
}

// Phase B: sum S partials; g[m,n] = sum_i S[b,i,m]*(wr + i wi)[i,o,m,n];
// u[m,w] = (1/256)*(g[m,0] + 2*sum_{n=1..15} g[m,n] e^{+2pi i n w/256})
// One block per (o,b); all 16 m handled here (2x hermitian fold and 1/256 folded into sG).
__global__ void k_mix(const float* __restrict__ Wr, const float* __restrict__ Wi) {
    __shared__ float2 sS[CIN * KM];  // [i][m]
    __shared__ float2 sG[KM * KM];   // [m][n], pre-scaled
    __shared__ float2 sT[256];
    int t = threadIdx.x;
    int o = blockIdx.x, b = blockIdx.y;
    sT[t] = twiddle(t);

    const float2* sp = &g_Sp[0][b][0][0];
    const int CHS = B * CIN * KM;  // chunk stride in float2
#pragma unroll
    for (int e = t; e < CIN * KM; e += 256) {
        float2 p0 = sp[e], p1 = sp[CHS + e], p2 = sp[2 * CHS + e], p3 = sp[3 * CHS + e];
        sS[e] = make_float2((p0.x + p1.x) + (p2.x + p3.x), (p0.y + p1.y) + (p2.y + p3.y));
    }
    __syncthreads();

    {
        int m = t >> 4, n = t & 15;
        float gr = 0.f, gi = 0.f;
        int off = (o * KM + m) * KM + n;   // [i=0][o][m][n]
#pragma unroll 4
        for (int i = 0; i < CIN; i++) {
            float2 s = sS[i * KM + m];
            float wr = Wr[off], wi = Wi[off];
            gr += s.x * wr - s.y * wi;
            gi += s.x * wi + s.y * wr;
            off += COUT * KM * KM;         // +8192
        }
        float sc = (n == 0) ? (1.f / 256.f) : (2.f / 256.f);
        sG[t] = make_float2(gr * sc, gi * sc);
    }
    __syncthreads();

    int w = t;
#pragma unroll
    for (int m = 0; m < KM; m++) {
        float2 g0 = sG[m * 16];
        float ur = g0.x, ui = g0.y;
#pragma unroll
        for (int nn = 1; nn < 16; nn++) {
            float2 cs = sT[(nn * w) & 255];
            float2 g = sG[m * 16 + nn];
            ur = fmaf(g.x, cs.x, ur); ur = fmaf(-g.y, cs.y, ur);
            ui = fmaf(g.x, cs.y, ui); ui = fmaf(g.y, cs.x, ui);
        }
        g_U[b][o][m][w] = make_float2(ur, ui);
    }
}

// Phase C: y[h,w] = sum_m ( ur'[m,w] cos(2pi m h/256) - ui'[m,w] sin(2pi m h/256) )
// (u' pre-scaled by 1/256). 4-fold row symmetry; packed f32x2 FMA:
// accE/accO accumulate (sum ur'*c, sum ui'*s) over even/odd m.
__global__ void __launch_bounds__(256, 5) k_synth(float* __restrict__ y) {
    __shared__ float2 sHT[13 * 16];   // per-block twiddles: [lh][m] = twiddle(m*h)
    int t = threadIdx.x;
    int o = blockIdx.x, b = blockIdx.y, hc = blockIdx.z;
    int h0 = hc * 13;

    if (t < 208) {
        int lh = t >> 4, m = t & 15;
        sHT[t] = twiddle(m * (h0 + lh));
    }

    ull u2[16];
    const ull* up = (const ull*)&g_U[b][o][0][t];
#pragma unroll
    for (int m = 0; m < 16; m++) u2[m] = up[m * W];
    __syncthreads();

    float* yp = y + ((size_t)(b * COUT + o) << 16) + t;
#pragma unroll 2
    for (int lh = 0; lh < 13; lh++) {
        int h = h0 + lh;
        const ull* tp = (const ull*)&sHT[lh * 16];
        ull aE = 0ull, aO = 0ull;
#pragma unroll
        for (int m = 0; m < 16; m += 2) {
            FMA_F32X2(aE, u2[m], tp[m], aE);
            FMA_F32X2(aO, u2[m + 1], tp[m + 1], aO);
        }
        float Ae, Be, Ao, Bo;
        asm("mov.b64 {%0, %1}, %2;" : "=f"(Ae), "=f"(Be) : "l"(aE));
        asm("mov.b64 {%0, %1}, %2;" : "=f"(Ao), "=f"(Bo) : "l"(aO));
        float u1 = Ae - Be, v1 = Ao - Bo;   // cos-part minus sin-part, even/odd m
        float p1 = Ae + Be, q1 = Ao + Bo;
        __stcs(&yp[h << 8], u1 + v1);               // row h
        __stcs(&yp[(128 + h) << 8], u1 - v1);       // row 128+h
        if (h > 0 && h < 64) {
            __stcs(&yp[(256 - h) << 8], p1 + q1);   // row 256-h
            __stcs(&yp[(128 - h) << 8], p1 - q1);   // row 128-h
        }
    }
}

extern "C" void kernel_launch(void* const* d_in, const int* in_sizes, int n_in,
                              void* d_out, int out_size) {
    (void)in_sizes; (void)n_in; (void)out_size;
    const float* x  = (const float*)d_in[0];
    const float* wr = (const float*)d_in[1];
    const float* wi = (const float*)d_in[2];
    float* y = (float*)d_out;

    k_analysis<<<dim3(CIN, B, 4), 256>>>(x);
    k_mix<<<dim3(COUT, B), 256>>>(wr, wi);
    k_synth<<<dim3(COUT, B, 5), 256>>>(y);
}